// round 1
// baseline (speedup 1.0000x reference)
#include <cuda_runtime.h>

// LR_23029614641373: logistic regression over concat one-hot(user,movie).
// logit = W[u] + W[N_USERS + m] + b;  out = [1-sigmoid, sigmoid]
// B = 4194304, N_USERS = 6040, table = 9923 floats (L1-resident).
//
// Each thread: one int4 load (2 rows of x), 4 gathers, 2 sigmoids,
// one float4 store. Pure HBM-streaming kernel (~67 MB total traffic).

#define N_USERS 6040

__global__ void __launch_bounds__(256) lr_pairs_kernel(
    const int4* __restrict__ x2,      // [n2] = two (u,m) pairs packed
    const float* __restrict__ w,      // [9923]
    const float* __restrict__ bptr,   // [1]
    float4* __restrict__ out,         // [n2] = {1-p0, p0, 1-p1, p1}
    int n2)
{
    int i = blockIdx.x * blockDim.x + threadIdx.x;
    if (i >= n2) return;

    const float bias = __ldg(bptr);
    int4 v = x2[i];

    float l0 = __ldg(w + v.x) + __ldg(w + N_USERS + v.y) + bias;
    float l1 = __ldg(w + v.z) + __ldg(w + N_USERS + v.w) + bias;

    // sigmoid via MUFU exp; rel-err budget is 1e-3, fast math is fine
    float p0 = __fdividef(1.0f, 1.0f + __expf(-l0));
    float p1 = __fdividef(1.0f, 1.0f + __expf(-l1));

    out[i] = make_float4(1.0f - p0, p0, 1.0f - p1, p1);
}

// Scalar tail kernel in case the row count is ever odd (B is even here,
// but keep kernel_launch shape-generic).
__global__ void lr_tail_kernel(
    const int2* __restrict__ x,
    const float* __restrict__ w,
    const float* __restrict__ bptr,
    float2* __restrict__ out,
    int start, int n)
{
    int i = start + blockIdx.x * blockDim.x + threadIdx.x;
    if (i >= n) return;
    int2 v = x[i];
    float l = __ldg(w + v.x) + __ldg(w + N_USERS + v.y) + __ldg(bptr);
    float p = __fdividef(1.0f, 1.0f + __expf(-l));
    out[i] = make_float2(1.0f - p, p);
}

extern "C" void kernel_launch(void* const* d_in, const int* in_sizes, int n_in,
                              void* d_out, int out_size)
{
    const int*   x = (const int*)d_in[0];     // [B, 2] int32
    const float* W = (const float*)d_in[1];   // [1, 9923]
    const float* b = (const float*)d_in[2];   // [1]
    float* out = (float*)d_out;               // [B, 2]

    int B  = in_sizes[0] / 2;   // rows
    int n2 = B / 2;             // pairs of rows

    if (n2 > 0) {
        int threads = 256;
        int blocks = (n2 + threads - 1) / threads;
        lr_pairs_kernel<<<blocks, threads>>>(
            (const int4*)x, W, b, (float4*)out, n2);
    }
    if (B & 1) {
        lr_tail_kernel<<<1, 32>>>(
            (const int2*)x, W, b, (float2*)out, 2 * n2, B);
    }
}

// round 2
// speedup vs baseline: 1.2214x; 1.2214x over previous
#include <cuda_runtime.h>

// LR_23029614641373: logit = W[u] + W[N_USERS + m] + b; out = [1-p, p]
// B = 4194304 rows. W table = 9923 floats (39.7 KB) -> staged in SMEM;
// gathers become LDS (conflict degree ~3-4) instead of scattered LDG
// (~32 L1 wavefronts each). Streaming int4 in / float4 out.

#define N_USERS 6040
#define TABLE   9923
#define NTHREADS 512
#define NBLOCKS_PER_SM 4

__global__ void __launch_bounds__(NTHREADS, NBLOCKS_PER_SM) lr_smem_kernel(
    const int4* __restrict__ x2,      // [n2] two (u,m) rows per int4
    const float* __restrict__ w,      // [9923]
    const float* __restrict__ bptr,   // [1]
    float4* __restrict__ out,         // [n2] {1-p0,p0,1-p1,p1}
    int n2)
{
    __shared__ float sw[TABLE];
    #pragma unroll
    for (int i = threadIdx.x; i < TABLE; i += NTHREADS)
        sw[i] = w[i];
    __syncthreads();

    const float bias = __ldg(bptr);
    const int stride = gridDim.x * blockDim.x;
    int i = blockIdx.x * blockDim.x + threadIdx.x;

    if (i >= n2) return;

    // software pipeline: keep next int4 load in flight while computing current
    int4 v = x2[i];
    int inext = i + stride;
    while (true) {
        int4 vn;
        bool has_next = (inext < n2);
        if (has_next) vn = x2[inext];   // issued before the dependent chain below

        float l0 = sw[v.x] + sw[N_USERS + v.y] + bias;
        float l1 = sw[v.z] + sw[N_USERS + v.w] + bias;

        // p = 1/(1+e^-l);  1-p = e^-l * p   (one MUFU exp + one rcp per row)
        float e0 = __expf(-l0);
        float e1 = __expf(-l1);
        float p0 = __frcp_rn(1.0f + e0);
        float p1 = __frcp_rn(1.0f + e1);

        out[i] = make_float4(e0 * p0, p0, e1 * p1, p1);

        if (!has_next) break;
        i = inext;
        inext += stride;
        v = vn;
    }
}

// Rare odd-row tail (B here is even); reads W straight from gmem.
__global__ void lr_tail_kernel(
    const int2* __restrict__ x,
    const float* __restrict__ w,
    const float* __restrict__ bptr,
    float2* __restrict__ out,
    int start, int n)
{
    int i = start + blockIdx.x * blockDim.x + threadIdx.x;
    if (i >= n) return;
    int2 v = x[i];
    float l = __ldg(w + v.x) + __ldg(w + N_USERS + v.y) + __ldg(bptr);
    float e = __expf(-l);
    float p = __frcp_rn(1.0f + e);
    out[i] = make_float2(e * p, p);
}

extern "C" void kernel_launch(void* const* d_in, const int* in_sizes, int n_in,
                              void* d_out, int out_size)
{
    const int*   x = (const int*)d_in[0];     // [B, 2] int32
    const float* W = (const float*)d_in[1];   // [1, 9923]
    const float* b = (const float*)d_in[2];   // [1]
    float* out = (float*)d_out;               // [B, 2]

    int B  = in_sizes[0] / 2;
    int n2 = B / 2;

    if (n2 > 0) {
        int max_blocks = 148 * NBLOCKS_PER_SM;           // persistent-ish grid
        int blocks = (n2 + NTHREADS - 1) / NTHREADS;
        if (blocks > max_blocks) blocks = max_blocks;
        lr_smem_kernel<<<blocks, NTHREADS>>>(
            (const int4*)x, W, b, (float4*)out, n2);
    }
    if (B & 1) {
        lr_tail_kernel<<<1, 32>>>(
            (const int2*)x, W, b, (float2*)out, 2 * n2, B);
    }
}